// round 14
// baseline (speedup 1.0000x reference)
#include <cuda_runtime.h>
#include <cstdint>
#include <math.h>

#define NN 50000
#define EE 800000
#define TOT (EE + NN)

// ---------------- device scratch (no allocations allowed) ----------------
__device__ __align__(16) float g_h1[NN * 128];   // layer-1 linear output
__device__ __align__(16) float g_as1[NN * 4];    // per-node attn src terms (4 heads)
__device__ __align__(16) float g_ad1[NN * 4];    // per-node attn dst terms
__device__ __align__(16) float g_h2[NN * 2];     // layer-2 linear output
__device__ float g_as2[NN];
__device__ float g_ad2[NN];
__device__ int g_deg[NN];
__device__ int g_rowptr[NN + 1];
__device__ int g_cursor[NN];
__device__ int g_csr[TOT];

__device__ __forceinline__ float lrelu(float x) { return x > 0.f ? x : 0.2f * x; }

// ---------------- CSR build ----------------
__global__ void k_hist(const int* __restrict__ ei) {
    int i = blockIdx.x * blockDim.x + threadIdx.x;
    if (i < EE) {
        atomicAdd(&g_deg[ei[EE + i]], 1);      // dst of edge i
    } else if (i < TOT) {
        atomicAdd(&g_deg[i - EE], 1);          // self loop
    }
}

__global__ void k_scan() {
    __shared__ int part[1024];
    int t = threadIdx.x;
    const int C = (NN + 1023) / 1024;  // 49
    int lo = t * C;
    int hi = lo + C;
    if (hi > NN) hi = NN;
    int s = 0;
    for (int i = lo; i < hi; i++) s += g_deg[i];
    part[t] = s;
    __syncthreads();
    for (int off = 1; off < 1024; off <<= 1) {
        int v = (t >= off) ? part[t - off] : 0;
        __syncthreads();
        part[t] += v;
        __syncthreads();
    }
    int run = (t > 0) ? part[t - 1] : 0;
    for (int i = lo; i < hi; i++) {
        g_rowptr[i] = run;
        g_cursor[i] = run;
        run += g_deg[i];
    }
    if (t == 1023) g_rowptr[NN] = part[1023];
}

__global__ void k_scatter(const int* __restrict__ ei) {
    int i = blockIdx.x * blockDim.x + threadIdx.x;
    if (i < EE) {
        int src = ei[i];
        int dst = ei[EE + i];
        int pos = atomicAdd(&g_cursor[dst], 1);
        g_csr[pos] = src;
    } else if (i < TOT) {
        int v = i - EE;
        int pos = atomicAdd(&g_cursor[v], 1);
        g_csr[pos] = v;  // self loop
    }
}

// ---------------- GEMM1 + attn terms: h1 = x @ W1, as1/ad1 fused -----------
// PROVEN scalar-FFMA mainloop (one warp/SMSP saturates the fp32 pipe).
// Block: 64 rows x 128 cols; 256 threads; each thread 8 rows x 4 cols.
// Whole W1 (64KB) + padded x-tile (33KB) in dynamic smem.
__global__ void __launch_bounds__(256) k_gemm1(const float* __restrict__ x,
                                               const float* __restrict__ W,
                                               const float* __restrict__ asrc,
                                               const float* __restrict__ adst) {
    extern __shared__ float sm[];
    float* Ws = sm;            // 16384 floats
    float* xs = sm + 16384;    // 64 * 132 floats (padded stride kills bank conflicts)
    int tid = threadIdx.x;
    int row0 = blockIdx.x * 64;

    const float4* W4 = (const float4*)W;
    float4* Ws4 = (float4*)Ws;
    for (int i = tid; i < 4096; i += 256) Ws4[i] = W4[i];
    for (int i = tid; i < 2048; i += 256) {
        int r = i >> 5, c4 = i & 31;
        float4 v;
        if (row0 + r < NN) v = ((const float4*)x)[(row0 + r) * 32 + c4];
        else v = make_float4(0.f, 0.f, 0.f, 0.f);
        *(float4*)&xs[r * 132 + c4 * 4] = v;
    }
    __syncthreads();

    int tx = tid & 31, ty = tid >> 5;
    float acc[8][4];
#pragma unroll
    for (int r = 0; r < 8; r++) { acc[r][0] = acc[r][1] = acc[r][2] = acc[r][3] = 0.f; }

    const float4* Wv = (const float4*)Ws;
#pragma unroll 8
    for (int k = 0; k < 128; k++) {
        float4 w = Wv[k * 32 + tx];
#pragma unroll
        for (int r = 0; r < 8; r++) {
            float xv = xs[(ty * 8 + r) * 132 + k];
            acc[r][0] = fmaf(xv, w.x, acc[r][0]);
            acc[r][1] = fmaf(xv, w.y, acc[r][1]);
            acc[r][2] = fmaf(xv, w.z, acc[r][2]);
            acc[r][3] = fmaf(xv, w.w, acc[r][3]);
        }
    }

    // epilogue: store h1 + fused attention terms (as1/ad1)
    float4 av = ((const float4*)asrc)[tx];
    float4 dv = ((const float4*)adst)[tx];
#pragma unroll
    for (int r = 0; r < 8; r++) {
        int row = row0 + ty * 8 + r;
        if (row < NN)
            ((float4*)g_h1)[row * 32 + tx] =
                make_float4(acc[r][0], acc[r][1], acc[r][2], acc[r][3]);
        float s = acc[r][0] * av.x + acc[r][1] * av.y + acc[r][2] * av.z + acc[r][3] * av.w;
        float d = acc[r][0] * dv.x + acc[r][1] * dv.y + acc[r][2] * dv.z + acc[r][3] * dv.w;
        s += __shfl_down_sync(0xffffffffu, s, 4);
        d += __shfl_down_sync(0xffffffffu, d, 4);
        s += __shfl_down_sync(0xffffffffu, s, 2);
        d += __shfl_down_sync(0xffffffffu, d, 2);
        s += __shfl_down_sync(0xffffffffu, s, 1);
        d += __shfl_down_sync(0xffffffffu, d, 1);
        if ((tx & 7) == 0 && row < NN) {
            g_as1[row * 4 + (tx >> 3)] = s;
            g_ad1[row * 4 + (tx >> 3)] = d;
        }
    }
}

// ---------------- layer-1 softmax agg + relu + layer-2 linear (warp/dst) ----
// Softmax computed WITHOUT max-shift (shift-invariant; logits are O(1) here,
// so exp() cannot overflow) -> single pass over edges.
__global__ void k_agg1(const float* __restrict__ b1,
                       const float* __restrict__ W2,
                       const float* __restrict__ asrc2,
                       const float* __restrict__ adst2) {
    int g = blockIdx.x * blockDim.x + threadIdx.x;
    int n = g >> 5, lane = g & 31;
    if (n >= NN) return;
    int beg = g_rowptr[n], end = g_rowptr[n + 1];
    float4 ad = *(const float4*)&g_ad1[n * 4];

    // single pass: lanes map channels; iterate edges serially (warp-uniform),
    // accumulate p and p*h
    float a0 = 0.f, a1 = 0.f, a2 = 0.f, a3 = 0.f;
    float d0 = 0.f, d1 = 0.f, d2 = 0.f, d3 = 0.f;
    for (int j = beg; j < end; j++) {
        int s = g_csr[j];                            // uniform across warp -> broadcast
        float4 avv = *(const float4*)&g_as1[s * 4];  // uniform -> broadcast
        float p0 = __expf(lrelu(avv.x + ad.x));
        float p1 = __expf(lrelu(avv.y + ad.y));
        float p2 = __expf(lrelu(avv.z + ad.z));
        float p3 = __expf(lrelu(avv.w + ad.w));
        const float* hr = &g_h1[s * 128];
        a0 = fmaf(p0, hr[lane], a0);
        a1 = fmaf(p1, hr[32 + lane], a1);
        a2 = fmaf(p2, hr[64 + lane], a2);
        a3 = fmaf(p3, hr[96 + lane], a3);
        d0 += p0; d1 += p1; d2 += p2; d3 += p3;
    }
    float o0 = fmaxf(a0 / (d0 + 1e-16f) + __ldg(&b1[lane]), 0.f);
    float o1 = fmaxf(a1 / (d1 + 1e-16f) + __ldg(&b1[32 + lane]), 0.f);
    float o2 = fmaxf(a2 / (d2 + 1e-16f) + __ldg(&b1[64 + lane]), 0.f);
    float o3 = fmaxf(a3 / (d3 + 1e-16f) + __ldg(&b1[96 + lane]), 0.f);

    // fused layer-2 linear: c = o @ W2  (W2 is [128,2] row-major)
    float c0 = o0 * __ldg(&W2[lane * 2])            + o1 * __ldg(&W2[(32 + lane) * 2])
             + o2 * __ldg(&W2[(64 + lane) * 2])     + o3 * __ldg(&W2[(96 + lane) * 2]);
    float c1 = o0 * __ldg(&W2[lane * 2 + 1])        + o1 * __ldg(&W2[(32 + lane) * 2 + 1])
             + o2 * __ldg(&W2[(64 + lane) * 2 + 1]) + o3 * __ldg(&W2[(96 + lane) * 2 + 1]);
#pragma unroll
    for (int off = 16; off; off >>= 1) {
        c0 += __shfl_xor_sync(0xffffffffu, c0, off);
        c1 += __shfl_xor_sync(0xffffffffu, c1, off);
    }
    if (lane == 0) {
        g_h2[2 * n]     = c0;
        g_h2[2 * n + 1] = c1;
        g_as2[n] = c0 * __ldg(&asrc2[0]) + c1 * __ldg(&asrc2[1]);
        g_ad2[n] = c0 * __ldg(&adst2[0]) + c1 * __ldg(&adst2[1]);
    }
}

// ---------------- layer-2 aggregation + log_softmax (warp per dst) ----------
// Same no-max-shift single pass.
__global__ void k_agg2(const float* __restrict__ b2, float* __restrict__ out) {
    int g = blockIdx.x * blockDim.x + threadIdx.x;
    int n = g >> 5, lane = g & 31;
    if (n >= NN) return;
    int beg = g_rowptr[n], end = g_rowptr[n + 1];
    float adv = g_ad2[n];

    float a0 = 0.f, a1 = 0.f, den = 0.f;
    for (int j = beg + lane; j < end; j += 32) {
        int s = g_csr[j];
        float p = __expf(lrelu(g_as2[s] + adv));
        float2 hv = *(const float2*)&g_h2[2 * s];
        a0 = fmaf(p, hv.x, a0);
        a1 = fmaf(p, hv.y, a1);
        den += p;
    }
#pragma unroll
    for (int off = 16; off; off >>= 1) {
        a0 += __shfl_xor_sync(0xffffffffu, a0, off);
        a1 += __shfl_xor_sync(0xffffffffu, a1, off);
        den += __shfl_xor_sync(0xffffffffu, den, off);
    }
    if (lane == 0) {
        float o0 = a0 / (den + 1e-16f) + b2[0];
        float o1 = a1 / (den + 1e-16f) + b2[1];
        float mm = fmaxf(o0, o1);
        float lse = mm + logf(expf(o0 - mm) + expf(o1 - mm));
        out[2 * n]     = o0 - lse;
        out[2 * n + 1] = o1 - lse;
    }
}

// ---------------- launch ----------------
// CSR build (depends only on edge_index) is forked onto a non-blocking
// stream and runs CONCURRENTLY with k_gemm1 (depends only on x/W1); both
// join before k_agg1. Standard capture-fork pattern: event-record on the
// origin stream -> wait on s1 -> work on s1 -> event-record on s1 -> wait
// on origin. Stream/events are created once (host-side resources only; no
// device allocations) and the same GPU work is issued on every call.
extern "C" void kernel_launch(void* const* d_in, const int* in_sizes, int n_in,
                              void* d_out, int out_size) {
    (void)in_sizes; (void)n_in; (void)out_size;
    const float* x     = (const float*)d_in[0];
    const int*   ei    = (const int*)d_in[1];   // [2, E]: first E = src, next E = dst
    const float* W1    = (const float*)d_in[2];
    const float* asrc1 = (const float*)d_in[3];
    const float* adst1 = (const float*)d_in[4];
    const float* b1    = (const float*)d_in[5];
    const float* W2    = (const float*)d_in[6];
    const float* asrc2 = (const float*)d_in[7];
    const float* adst2 = (const float*)d_in[8];
    const float* b2    = (const float*)d_in[9];
    float* out = (float*)d_out;

    static cudaStream_t s1 = nullptr;
    static cudaEvent_t evFork = nullptr, evJoin = nullptr;
    if (s1 == nullptr) {
        cudaStreamCreateWithFlags(&s1, cudaStreamNonBlocking);
        cudaEventCreateWithFlags(&evFork, cudaEventDisableTiming);
        cudaEventCreateWithFlags(&evJoin, cudaEventDisableTiming);
    }

    cudaFuncSetAttribute(k_gemm1, cudaFuncAttributeMaxDynamicSharedMemorySize, 99328);

    void* degPtr = nullptr;
    cudaGetSymbolAddress(&degPtr, g_deg);

    // fork: CSR build on s1, concurrent with gemm1 on the main stream
    cudaEventRecord(evFork, 0);
    cudaStreamWaitEvent(s1, evFork, 0);
    cudaMemsetAsync(degPtr, 0, NN * sizeof(int), s1);
    k_hist<<<(TOT + 255) / 256, 256, 0, s1>>>(ei);
    k_scan<<<1, 1024, 0, s1>>>();
    k_scatter<<<(TOT + 255) / 256, 256, 0, s1>>>(ei);
    cudaEventRecord(evJoin, s1);

    // layer 1 linear (FFMA, proven) + fused attn terms — overlaps CSR build
    k_gemm1<<<(NN + 63) / 64, 256, 99328>>>(x, W1, asrc1, adst1);

    // join: agg1 needs both gemm1 outputs and the CSR
    cudaStreamWaitEvent(0, evJoin, 0);

    // layer-1 softmax agg + relu + layer-2 linear fused
    k_agg1<<<(NN * 32 + 255) / 256, 256>>>(b1, W2, asrc2, adst2);
    // layer-2 aggregation + log_softmax
    k_agg2<<<(NN * 32 + 255) / 256, 256>>>(b2, out);
}

// round 15
// speedup vs baseline: 1.0108x; 1.0108x over previous
#include <cuda_runtime.h>
#include <cstdint>
#include <math.h>

#define NN 50000
#define EE 800000
#define TOT (EE + NN)

// ---------------- device scratch (no allocations allowed) ----------------
__device__ __align__(16) float g_h1[NN * 128];   // layer-1 linear output
__device__ __align__(16) float g_as1[NN * 4];    // per-node attn src terms (4 heads)
__device__ __align__(16) float g_ad1[NN * 4];    // per-node attn dst terms
__device__ __align__(16) float g_h2[NN * 2];     // layer-2 linear output
__device__ float g_as2[NN];
__device__ float g_ad2[NN];
__device__ int g_deg[NN];
__device__ int g_rowptr[NN + 1];
__device__ int g_cursor[NN];
__device__ int g_csr[TOT];
__device__ int g_dstv[TOT];                      // dst node of each CSR slot
__device__ __align__(16) float4 g_p[TOT];        // per-edge softmax weights (4 heads)

__device__ __forceinline__ float lrelu(float x) { return x > 0.f ? x : 0.2f * x; }

// ---------------- CSR build ----------------
__global__ void k_hist(const int* __restrict__ ei) {
    int i = blockIdx.x * blockDim.x + threadIdx.x;
    if (i < EE) {
        atomicAdd(&g_deg[ei[EE + i]], 1);      // dst of edge i
    } else if (i < TOT) {
        atomicAdd(&g_deg[i - EE], 1);          // self loop
    }
}

__global__ void k_scan() {
    __shared__ int part[1024];
    int t = threadIdx.x;
    const int C = (NN + 1023) / 1024;  // 49
    int lo = t * C;
    int hi = lo + C;
    if (hi > NN) hi = NN;
    int s = 0;
    for (int i = lo; i < hi; i++) s += g_deg[i];
    part[t] = s;
    __syncthreads();
    for (int off = 1; off < 1024; off <<= 1) {
        int v = (t >= off) ? part[t - off] : 0;
        __syncthreads();
        part[t] += v;
        __syncthreads();
    }
    int run = (t > 0) ? part[t - 1] : 0;
    for (int i = lo; i < hi; i++) {
        g_rowptr[i] = run;
        g_cursor[i] = run;
        run += g_deg[i];
    }
    if (t == 1023) g_rowptr[NN] = part[1023];
}

__global__ void k_scatter(const int* __restrict__ ei) {
    int i = blockIdx.x * blockDim.x + threadIdx.x;
    if (i < EE) {
        int src = ei[i];
        int dst = ei[EE + i];
        int pos = atomicAdd(&g_cursor[dst], 1);
        g_csr[pos] = src;
        g_dstv[pos] = dst;
    } else if (i < TOT) {
        int v = i - EE;
        int pos = atomicAdd(&g_cursor[v], 1);
        g_csr[pos] = v;  // self loop
        g_dstv[pos] = v;
    }
}

// ---------------- GEMM1 + attn terms: h1 = x @ W1, as1/ad1 fused -----------
__global__ void __launch_bounds__(256) k_gemm1(const float* __restrict__ x,
                                               const float* __restrict__ W,
                                               const float* __restrict__ asrc,
                                               const float* __restrict__ adst) {
    extern __shared__ float sm[];
    float* Ws = sm;            // 16384 floats
    float* xs = sm + 16384;    // 64 * 132 floats (padded stride kills bank conflicts)
    int tid = threadIdx.x;
    int row0 = blockIdx.x * 64;

    const float4* W4 = (const float4*)W;
    float4* Ws4 = (float4*)Ws;
    for (int i = tid; i < 4096; i += 256) Ws4[i] = W4[i];
    for (int i = tid; i < 2048; i += 256) {
        int r = i >> 5, c4 = i & 31;
        float4 v;
        if (row0 + r < NN) v = ((const float4*)x)[(row0 + r) * 32 + c4];
        else v = make_float4(0.f, 0.f, 0.f, 0.f);
        *(float4*)&xs[r * 132 + c4 * 4] = v;
    }
    __syncthreads();

    int tx = tid & 31, ty = tid >> 5;
    float acc[8][4];
#pragma unroll
    for (int r = 0; r < 8; r++) { acc[r][0] = acc[r][1] = acc[r][2] = acc[r][3] = 0.f; }

    const float4* Wv = (const float4*)Ws;
#pragma unroll 8
    for (int k = 0; k < 128; k++) {
        float4 w = Wv[k * 32 + tx];
#pragma unroll
        for (int r = 0; r < 8; r++) {
            float xv = xs[(ty * 8 + r) * 132 + k];
            acc[r][0] = fmaf(xv, w.x, acc[r][0]);
            acc[r][1] = fmaf(xv, w.y, acc[r][1]);
            acc[r][2] = fmaf(xv, w.z, acc[r][2]);
            acc[r][3] = fmaf(xv, w.w, acc[r][3]);
        }
    }

    // epilogue: store h1 + fused attention terms (as1/ad1)
    float4 av = ((const float4*)asrc)[tx];
    float4 dv = ((const float4*)adst)[tx];
#pragma unroll
    for (int r = 0; r < 8; r++) {
        int row = row0 + ty * 8 + r;
        if (row < NN)
            ((float4*)g_h1)[row * 32 + tx] =
                make_float4(acc[r][0], acc[r][1], acc[r][2], acc[r][3]);
        float s = acc[r][0] * av.x + acc[r][1] * av.y + acc[r][2] * av.z + acc[r][3] * av.w;
        float d = acc[r][0] * dv.x + acc[r][1] * dv.y + acc[r][2] * dv.z + acc[r][3] * dv.w;
        s += __shfl_down_sync(0xffffffffu, s, 4);
        d += __shfl_down_sync(0xffffffffu, d, 4);
        s += __shfl_down_sync(0xffffffffu, s, 2);
        d += __shfl_down_sync(0xffffffffu, d, 2);
        s += __shfl_down_sync(0xffffffffu, s, 1);
        d += __shfl_down_sync(0xffffffffu, d, 1);
        if ((tx & 7) == 0 && row < NN) {
            g_as1[row * 4 + (tx >> 3)] = s;
            g_ad1[row * 4 + (tx >> 3)] = d;
        }
    }
}

// ---------------- per-edge softmax weights (edge-parallel, high MLP) --------
// p[j] = exp(lrelu(as1[src] + ad1[dst])), all 4 heads. No max-shift needed
// (logits are O(1); validated rel_err 6.8e-8 in R14).
__global__ void k_edgep() {
    int j = blockIdx.x * blockDim.x + threadIdx.x;
    if (j >= TOT) return;
    int s = g_csr[j];
    int n = g_dstv[j];
    float4 av = *(const float4*)&g_as1[s * 4];
    float4 dv = *(const float4*)&g_ad1[n * 4];
    float4 p;
    p.x = __expf(lrelu(av.x + dv.x));
    p.y = __expf(lrelu(av.y + dv.y));
    p.z = __expf(lrelu(av.z + dv.z));
    p.w = __expf(lrelu(av.w + dv.w));
    g_p[j] = p;
}

// ---------------- layer-1 agg + relu + layer-2 linear (warp/dst) ------------
// Serial edge loop now touches only LINEAR p[j]/csr[j] (software-pipelined
// one ahead) plus the h gather; expf and the as1 pointer-chase are gone.
__global__ void k_agg1(const float* __restrict__ b1,
                       const float* __restrict__ W2,
                       const float* __restrict__ asrc2,
                       const float* __restrict__ adst2) {
    int g = blockIdx.x * blockDim.x + threadIdx.x;
    int n = g >> 5, lane = g & 31;
    if (n >= NN) return;
    int beg = g_rowptr[n], end = g_rowptr[n + 1];

    float a0 = 0.f, a1 = 0.f, a2 = 0.f, a3 = 0.f;
    float d0 = 0.f, d1 = 0.f, d2 = 0.f, d3 = 0.f;

    int sN = g_csr[beg];        // every segment has >=1 entry (self loop)
    float4 pN = g_p[beg];
    for (int j = beg; j < end; j++) {
        int s = sN;
        float4 p = pN;
        if (j + 1 < end) {      // prefetch next iteration (linear addresses)
            sN = g_csr[j + 1];
            pN = g_p[j + 1];
        }
        const float* hr = &g_h1[s * 128];
        a0 = fmaf(p.x, hr[lane], a0);
        a1 = fmaf(p.y, hr[32 + lane], a1);
        a2 = fmaf(p.z, hr[64 + lane], a2);
        a3 = fmaf(p.w, hr[96 + lane], a3);
        d0 += p.x; d1 += p.y; d2 += p.z; d3 += p.w;
    }
    float o0 = fmaxf(a0 / (d0 + 1e-16f) + __ldg(&b1[lane]), 0.f);
    float o1 = fmaxf(a1 / (d1 + 1e-16f) + __ldg(&b1[32 + lane]), 0.f);
    float o2 = fmaxf(a2 / (d2 + 1e-16f) + __ldg(&b1[64 + lane]), 0.f);
    float o3 = fmaxf(a3 / (d3 + 1e-16f) + __ldg(&b1[96 + lane]), 0.f);

    // fused layer-2 linear: c = o @ W2  (W2 is [128,2] row-major)
    float c0 = o0 * __ldg(&W2[lane * 2])            + o1 * __ldg(&W2[(32 + lane) * 2])
             + o2 * __ldg(&W2[(64 + lane) * 2])     + o3 * __ldg(&W2[(96 + lane) * 2]);
    float c1 = o0 * __ldg(&W2[lane * 2 + 1])        + o1 * __ldg(&W2[(32 + lane) * 2 + 1])
             + o2 * __ldg(&W2[(64 + lane) * 2 + 1]) + o3 * __ldg(&W2[(96 + lane) * 2 + 1]);
#pragma unroll
    for (int off = 16; off; off >>= 1) {
        c0 += __shfl_xor_sync(0xffffffffu, c0, off);
        c1 += __shfl_xor_sync(0xffffffffu, c1, off);
    }
    if (lane == 0) {
        g_h2[2 * n]     = c0;
        g_h2[2 * n + 1] = c1;
        g_as2[n] = c0 * __ldg(&asrc2[0]) + c1 * __ldg(&asrc2[1]);
        g_ad2[n] = c0 * __ldg(&adst2[0]) + c1 * __ldg(&adst2[1]);
    }
}

// ---------------- layer-2 aggregation + log_softmax (warp per dst) ----------
__global__ void k_agg2(const float* __restrict__ b2, float* __restrict__ out) {
    int g = blockIdx.x * blockDim.x + threadIdx.x;
    int n = g >> 5, lane = g & 31;
    if (n >= NN) return;
    int beg = g_rowptr[n], end = g_rowptr[n + 1];
    float adv = g_ad2[n];

    float a0 = 0.f, a1 = 0.f, den = 0.f;
    for (int j = beg + lane; j < end; j += 32) {
        int s = g_csr[j];
        float p = __expf(lrelu(g_as2[s] + adv));
        float2 hv = *(const float2*)&g_h2[2 * s];
        a0 = fmaf(p, hv.x, a0);
        a1 = fmaf(p, hv.y, a1);
        den += p;
    }
#pragma unroll
    for (int off = 16; off; off >>= 1) {
        a0 += __shfl_xor_sync(0xffffffffu, a0, off);
        a1 += __shfl_xor_sync(0xffffffffu, a1, off);
        den += __shfl_xor_sync(0xffffffffu, den, off);
    }
    if (lane == 0) {
        float o0 = a0 / (den + 1e-16f) + b2[0];
        float o1 = a1 / (den + 1e-16f) + b2[1];
        float mm = fmaxf(o0, o1);
        float lse = mm + logf(expf(o0 - mm) + expf(o1 - mm));
        out[2 * n]     = o0 - lse;
        out[2 * n + 1] = o1 - lse;
    }
}

// ---------------- launch ----------------
// CSR build (only needs edge_index) forks onto a non-blocking stream and
// overlaps k_gemm1; both join before k_edgep (needs as1/ad1 + CSR).
extern "C" void kernel_launch(void* const* d_in, const int* in_sizes, int n_in,
                              void* d_out, int out_size) {
    (void)in_sizes; (void)n_in; (void)out_size;
    const float* x     = (const float*)d_in[0];
    const int*   ei    = (const int*)d_in[1];   // [2, E]: first E = src, next E = dst
    const float* W1    = (const float*)d_in[2];
    const float* asrc1 = (const float*)d_in[3];
    const float* adst1 = (const float*)d_in[4];
    const float* b1    = (const float*)d_in[5];
    const float* W2    = (const float*)d_in[6];
    const float* asrc2 = (const float*)d_in[7];
    const float* adst2 = (const float*)d_in[8];
    const float* b2    = (const float*)d_in[9];
    float* out = (float*)d_out;

    static cudaStream_t s1 = nullptr;
    static cudaEvent_t evFork = nullptr, evJoin = nullptr;
    if (s1 == nullptr) {
        cudaStreamCreateWithFlags(&s1, cudaStreamNonBlocking);
        cudaEventCreateWithFlags(&evFork, cudaEventDisableTiming);
        cudaEventCreateWithFlags(&evJoin, cudaEventDisableTiming);
    }

    cudaFuncSetAttribute(k_gemm1, cudaFuncAttributeMaxDynamicSharedMemorySize, 99328);

    void* degPtr = nullptr;
    cudaGetSymbolAddress(&degPtr, g_deg);

    // fork: CSR build on s1, concurrent with gemm1 on the main stream
    cudaEventRecord(evFork, 0);
    cudaStreamWaitEvent(s1, evFork, 0);
    cudaMemsetAsync(degPtr, 0, NN * sizeof(int), s1);
    k_hist<<<(TOT + 255) / 256, 256, 0, s1>>>(ei);
    k_scan<<<1, 1024, 0, s1>>>();
    k_scatter<<<(TOT + 255) / 256, 256, 0, s1>>>(ei);
    cudaEventRecord(evJoin, s1);

    // layer 1 linear (FFMA, proven) + fused attn terms — overlaps CSR build
    k_gemm1<<<(NN + 63) / 64, 256, 99328>>>(x, W1, asrc1, adst1);

    // join: everything after needs both gemm1 outputs and the CSR
    cudaStreamWaitEvent(0, evJoin, 0);

    // per-edge softmax weights (edge-parallel)
    k_edgep<<<(TOT + 255) / 256, 256>>>();
    // layer-1 agg + relu + layer-2 linear fused
    k_agg1<<<(NN * 32 + 255) / 256, 256>>>(b1, W2, asrc2, adst2);
    // layer-2 aggregation + log_softmax
    k_agg2<<<(NN * 32 + 255) / 256, 256>>>(b2, out);
}